// round 15
// baseline (speedup 1.0000x reference)
#include <cuda_runtime.h>
#include <cuda.h>
#include <cuda_bf16.h>
#include <cstdint>
#include <cstddef>

// ===================== problem constants =====================
static constexpr int IN_F    = 4096;
static constexpr int OUT_F   = 4096;
static constexpr int RANK    = 16;
static constexpr int M_TOTAL = 4 * 2048;     // 8192 rows of x
static constexpr int PK      = 2 * IN_F;     // packed K (hi|lo per 32-group) = 8192

static constexpr int THREADS  = 256;
static constexpr int NCLUST   = 74;          // persistent clusters (148 CTAs)
static constexpr int NTILES   = (M_TOTAL / 256) * (OUT_F / 256);   // 512
static constexpr int M_TILES  = M_TOTAL / 256;                     // 32
static constexpr unsigned PREP_WARPS_TC = 148u * 7u;               // 1036
static constexpr unsigned PREP_WARPS_FB = 148u * 8u;               // 1184

// ---- tcgen05 cg2 path ----
static constexpr int KC_TC = 32;             // k-elems per stage
static constexpr int NK_TC = IN_F / KC_TC;   // 128 k-iters per tile
static constexpr int SW_OFF  = 16384;        // W slice offset within stage
static constexpr int STG_TC  = 32768;        // per-CTA stage bytes (X 16K + W 16K)
static constexpr int NSTAGE  = 5;
static constexpr int HDR_TC  = 1024;
static constexpr int SMEM_DYN = HDR_TC + NSTAGE * STG_TC;   // 164864

// idesc cg2 kind::f16: bf16 x bf16 -> f32, M=256, N=256, K-major both
static constexpr uint32_t IDESC_CG2 =
    (1u << 4) | (1u << 7) | (1u << 10) | ((256 / 8u) << 17) | ((256 / 16u) << 24);

// ---- fallback (mma.sync) ----
static constexpr int KC_FB = 32;
static constexpr int NK_FB = IN_F / KC_FB;   // 128
static constexpr int ROWH  = 40;
static constexpr int AH_B  = 0;
static constexpr int AL_B  = 128 * ROWH * 2;
static constexpr int BH_B  = 2 * 128 * ROWH * 2;
static constexpr int BL_B  = 3 * 128 * ROWH * 2;
static constexpr int STG_FB = 4 * 128 * ROWH * 2;    // 40960
static constexpr int NSTAGE_FB = 3;

// ===================== scratch (__device__ globals; no cudaMalloc) ===========
__device__ __nv_bfloat16 g_Xp[(size_t)M_TOTAL * PK];   // 128 MB
__device__ __nv_bfloat16 g_Wp[(size_t)OUT_F * PK];     // 64 MB
__device__ unsigned g_cnt[132];   // [0..127] chunk-ready counters, [128] fb barrier

// ===================== common helpers =====================
__device__ __forceinline__ uint32_t smem_u32(const void* p) {
    uint32_t a;
    asm("{ .reg .u64 t; cvta.to.shared.u64 t, %1; cvt.u32.u64 %0, t; }" : "=r"(a) : "l"(p));
    return a;
}
__device__ __forceinline__ void cp16(uint32_t sdst, const void* gsrc) {
    asm volatile("cp.async.cg.shared.global [%0], [%1], 16;" :: "r"(sdst), "l"(gsrc));
}
#define CP_COMMIT() asm volatile("cp.async.commit_group;" ::: "memory")
#define CP_WAIT(n)  asm volatile("cp.async.wait_group %0;" :: "n"(n) : "memory")

// ===================== fused prep (runs inside gemm kernel) ==================
// Warp-granular, k-chunk-major. Chunk k: X cols [k*32,(k+1)*32) of all 8192 rows,
// W' cols same of all 4096 rows, written packed [hi32|lo32] at cols k*64..k*64+63.
// After a warp finishes chunk k it arrives on g_cnt[k]; counter full => ready
// (each warp processes chunks in order => counters fill in order).
__device__ __forceinline__ void prep_warp(
    int gw, int nwarps, int lane,
    const float* __restrict__ x, const float* __restrict__ W,
    const float* __restrict__ U, const float* __restrict__ s,
    const float* __restrict__ V)
{
    const float s_l = (lane < 16) ? s[lane] : 0.f;
    for (int k = 0; k < 128; ++k) {
        // ---- X rows ----
        for (int row = gw; row < M_TOTAL; row += nwarps) {
            float f = x[(size_t)row * IN_F + k * 32 + lane];
            __nv_bfloat16 hb = __float2bfloat16(f);
            float res = f - __bfloat162float(hb);
            __nv_bfloat16 lb = __float2bfloat16(res);
            size_t base = (size_t)row * PK + (size_t)k * 64 + lane;
            g_Xp[base]      = hb;
            g_Xp[base + 32] = lb;
        }
        // ---- V block for this chunk: lane holds V[k*32+lane][0..15] ----
        float v[16];
        {
            const float4* vp = reinterpret_cast<const float4*>(
                V + (size_t)(k * 32 + lane) * RANK);
            float4 a0 = vp[0], a1 = vp[1], a2 = vp[2], a3 = vp[3];
            v[0]=a0.x; v[1]=a0.y; v[2]=a0.z; v[3]=a0.w;
            v[4]=a1.x; v[5]=a1.y; v[6]=a1.z; v[7]=a1.w;
            v[8]=a2.x; v[9]=a2.y; v[10]=a2.z; v[11]=a2.w;
            v[12]=a3.x; v[13]=a3.y; v[14]=a3.z; v[15]=a3.w;
        }
        // ---- W' rows ----
        for (int row = gw; row < OUT_F; row += nwarps) {
            float u = (lane < 16) ? U[(size_t)row * RANK + lane] * s_l : 0.f;
            float acc = W[(size_t)row * IN_F + k * 32 + lane];
            #pragma unroll
            for (int r = 0; r < 16; ++r)
                acc += __shfl_sync(0xFFFFFFFFu, u, r) * v[r];
            __nv_bfloat16 hb = __float2bfloat16(acc);
            float res = acc - __bfloat162float(hb);
            __nv_bfloat16 lb = __float2bfloat16(res);
            size_t base = (size_t)row * PK + (size_t)k * 64 + lane;
            g_Wp[base]      = hb;
            g_Wp[base + 32] = lb;
        }
        __threadfence();
        __syncwarp();
        if (lane == 0) atomicAdd(&g_cnt[k], 1u);
    }
}

// ===================== tcgen05/TMA machinery (sm_103a cubin only) =============
#if defined(__CUDA_ARCH_FEAT_SM103_ALL)
__device__ __forceinline__ uint32_t elect_one() {
    uint32_t p;
    asm volatile("{\n\t.reg .pred p;\n\telect.sync _|p, 0xFFFFFFFF;\n\tselp.b32 %0, 1, 0, p;\n\t}"
                 : "=r"(p));
    return p;
}
#define MBARRIER_INIT(addr, cnt) \
    asm volatile("mbarrier.init.shared.b64 [%0], %1;" :: "r"(addr), "r"(cnt) : "memory")
#define MBARRIER_ARRIVE(mbar) \
    asm volatile("mbarrier.arrive.shared.b64 _, [%0];" :: "r"((uint32_t)(mbar)) : "memory")
#define MBARRIER_ARRIVE_CLUSTER(mbar, trank) \
    asm volatile("{\n\t.reg .b32 ra;\n\t" \
                 "mapa.shared::cluster.u32 ra, %0, %1;\n\t" \
                 "mbarrier.arrive.shared::cluster.b64 _, [ra];\n\t}" \
                 :: "r"((uint32_t)(mbar)), "r"((uint32_t)(trank)) : "memory")
#define MBARRIER_EXPECT_TX(mbar, bytes) \
    asm volatile("mbarrier.arrive.expect_tx.shared.b64 _, [%0], %1;" \
                 :: "r"((uint32_t)(mbar)), "r"((uint32_t)(bytes)) : "memory")
#define MBARRIER_WAIT_PARITY(mbar, par) do {                                             \
    uint32_t _m = (uint32_t)(mbar); uint32_t _p = (uint32_t)(par); uint32_t _d;          \
    asm volatile("{\n\t.reg .pred p;\n\t"                                                \
        "mbarrier.try_wait.parity.acquire.cta.shared::cta.b64 p, [%1], %2;\n\t"          \
        "selp.b32 %0, 1, 0, p;\n\t}" : "=r"(_d) : "r"(_m), "r"(_p) : "memory");          \
    if (!_d) {                                                                           \
        asm volatile("{\n\t.reg .pred P1;\n\tWL_%=: \n\t"                                \
            "mbarrier.try_wait.parity.acquire.cta.shared::cta.b64 P1, [%0], %1, 0x989680;\n\t" \
            "@P1 bra.uni WD_%=;\n\tbra.uni WL_%=;\n\tWD_%=: \n\t}"                       \
            :: "r"(_m), "r"(_p) : "memory");                                             \
    }                                                                                    \
} while (0)
#define TMA_LOAD_3D_CG2(smem_addr, tmap, c0, c1, c2, mbar) \
    asm volatile( \
        "{\n\t.reg .b32 lb;\n\t" \
        "and.b32 lb, %5, 0xFEFFFFFF;\n\t" \
        "cp.async.bulk.tensor.3d.cta_group::2.shared::cluster.global" \
        ".tile.mbarrier::complete_tx::bytes " \
        "[%0], [%1, {%2, %3, %4}], [lb];\n\t}" \
        :: "r"((uint32_t)(smem_addr)), "l"(tmap), \
           "r"((int)(c0)), "r"((int)(c1)), "r"((int)(c2)), \
           "r"((uint32_t)(mbar)) : "memory")
#define TCGEN05_ALLOC_CG2(sa, n) \
    asm volatile("tcgen05.alloc.cta_group::2.sync.aligned.shared::cta.b32 [%0], %1;" \
                 :: "r"((uint32_t)(sa)), "r"((uint32_t)(n)) : "memory")
#define TCGEN05_RELQ_CG2() \
    asm volatile("tcgen05.relinquish_alloc_permit.cta_group::2.sync.aligned;")
#define TCGEN05_DEALLOC_CG2(t, n) \
    asm volatile("tcgen05.dealloc.cta_group::2.sync.aligned.b32 %0, %1;" \
                 :: "r"(t), "r"((uint32_t)(n)))
#define TCGEN05_COMMIT_MC_CG2(mb) \
    asm volatile("tcgen05.commit.cta_group::2.mbarrier::arrive::one.shared::cluster.multicast::cluster.b64 [%0], %1;" \
                 :: "r"((uint32_t)(mb)), "h"((uint16_t)3) : "memory")
#define TCGEN05_FENCE_AFTER()  asm volatile("tcgen05.fence::after_thread_sync;" ::: "memory")
#define TCGEN05_FENCE_BEFORE() asm volatile("tcgen05.fence::before_thread_sync;" ::: "memory")
#define TCGEN05_WAIT_LD()      asm volatile("tcgen05.wait::ld.sync.aligned;" ::: "memory")
#define CLUSTER_ARRIVE() asm volatile("barrier.cluster.arrive.aligned;" ::: "memory")
#define CLUSTER_WAIT()   asm volatile("barrier.cluster.wait.aligned;" ::: "memory")

// poll a prep chunk counter (only used during tile 0), then fence to async proxy
#define POLL_CHUNK(kk) do {                                                   \
    unsigned _v; const unsigned* _c = &g_cnt[(kk)];                           \
    while (true) {                                                            \
        asm volatile("ld.acquire.gpu.u32 %0, [%1];" : "=r"(_v) : "l"(_c));    \
        if (_v >= PREP_WARPS_TC) break;                                       \
        asm volatile("nanosleep.u32 128;");                                   \
    }                                                                         \
    asm volatile("fence.proxy.async;" ::: "memory");                          \
} while (0)

#define TCGEN05_LD_X32(r, ta) \
    asm volatile( \
        "tcgen05.ld.sync.aligned.32x32b.x32.b32 " \
        "{%0, %1, %2, %3, %4, %5, %6, %7, " \
        " %8, %9, %10, %11, %12, %13, %14, %15, " \
        " %16, %17, %18, %19, %20, %21, %22, %23, " \
        " %24, %25, %26, %27, %28, %29, %30, %31}, [%32];" \
        : "=r"((r)[0]),  "=r"((r)[1]),  "=r"((r)[2]),  "=r"((r)[3]), \
          "=r"((r)[4]),  "=r"((r)[5]),  "=r"((r)[6]),  "=r"((r)[7]), \
          "=r"((r)[8]),  "=r"((r)[9]),  "=r"((r)[10]), "=r"((r)[11]), \
          "=r"((r)[12]), "=r"((r)[13]), "=r"((r)[14]), "=r"((r)[15]), \
          "=r"((r)[16]), "=r"((r)[17]), "=r"((r)[18]), "=r"((r)[19]), \
          "=r"((r)[20]), "=r"((r)[21]), "=r"((r)[22]), "=r"((r)[23]), \
          "=r"((r)[24]), "=r"((r)[25]), "=r"((r)[26]), "=r"((r)[27]), \
          "=r"((r)[28]), "=r"((r)[29]), "=r"((r)[30]), "=r"((r)[31]) \
        : "r"(ta))

static constexpr uint64_t SMEM_DESC_BASE_SW128 =
    (uint64_t(2) << 61) | (uint64_t(1) << 46) | (uint64_t(64) << 32) | (uint64_t(1) << 16);
#define MAKE_SMEM_DESC(ba) (SMEM_DESC_BASE_SW128 | ((uint64_t)((ba) >> 4) & 0x3FFF))

__device__ __forceinline__ void mma_f16_ss_cg2(uint32_t d, uint64_t a, uint64_t b,
                                               uint32_t idesc, uint32_t acc) {
    asm volatile(
        "{\n\t.reg .pred p;\n\tsetp.ne.u32 p, %4, 0;\n\t"
        "tcgen05.mma.cta_group::2.kind::f16 [%0], %1, %2, %3, "
        "{%5, %5, %5, %5, %5, %5, %5, %5}, p;\n\t}"
        :: "r"(d), "l"(a), "l"(b), "r"(idesc), "r"(acc), "r"(0u) : "memory");
}
#else
__device__ __forceinline__ void ldm4(uint32_t* r, uint32_t addr) {
    asm volatile("ldmatrix.sync.aligned.m8n8.x4.shared.b16 {%0,%1,%2,%3}, [%4];"
                 : "=r"(r[0]), "=r"(r[1]), "=r"(r[2]), "=r"(r[3]) : "r"(addr));
}
__device__ __forceinline__ void mma16816(float* d, const uint32_t* a, const uint32_t* b) {
    asm volatile(
        "mma.sync.aligned.m16n8k16.row.col.f32.bf16.bf16.f32 "
        "{%0,%1,%2,%3}, {%4,%5,%6,%7}, {%8,%9}, {%0,%1,%2,%3};"
        : "+f"(d[0]), "+f"(d[1]), "+f"(d[2]), "+f"(d[3])
        : "r"(a[0]), "r"(a[1]), "r"(a[2]), "r"(a[3]), "r"(b[0]), "r"(b[1]));
}
#endif

// ===================== fused persistent kernel =====================
// grid (2, 74, 1), cluster (2,1,1), 256 threads.
// warp 0: MMA/TMA pipeline (rank0) / TMA producer (rank1)
// warps 1-3: prep only; warps 4-7: prep, then epilogue
__global__ void __launch_bounds__(THREADS, 1) __cluster_dims__(2, 1, 1)
gemm_kernel(float* __restrict__ out,
            const float* __restrict__ x, const float* __restrict__ W,
            const float* __restrict__ U, const float* __restrict__ s,
            const float* __restrict__ V,
            const __grid_constant__ CUtensorMap tmx,
            const __grid_constant__ CUtensorMap tmw)
{
    extern __shared__ char smem[];
    const uint32_t sb = smem_u32(smem);
    const int tid  = threadIdx.x;
    const int lane = tid & 31;
    const int wid  = tid >> 5;
    const int rank = (int)blockIdx.x;
    const int cid  = (int)blockIdx.y;             // cluster id 0..73
    const int lin  = rank + 2 * cid;              // linear CTA id 0..147
    const int NLOC = (NTILES - 1 - cid) / NCLUST + 1;   // 6 or 7 local tiles

#if defined(__CUDA_ARCH_FEAT_SM103_ALL)
    const uint32_t FULL = sb + 64;    // 5 slots
    const uint32_t MBM  = sb + 128;   // 4 slots
    const uint32_t TILE = sb + 192;   // 2 slots (tile-done, multicast)
    const uint32_t EPI  = sb + 256;   // 2 slots (buffer free, count 2, on rank0)

    if (tid == 0) {
        for (int i = 0; i < 5; ++i) MBARRIER_INIT(FULL + i * 8, 1);
        for (int i = 0; i < 4; ++i) MBARRIER_INIT(MBM + i * 8, 1);
        for (int i = 0; i < 2; ++i) MBARRIER_INIT(TILE + i * 8, 1);
        for (int i = 0; i < 2; ++i) MBARRIER_INIT(EPI + i * 8, 2);
    }
    if (wid == 0) TCGEN05_ALLOC_CG2(sb + 0, 512);   // two 256-col accumulators
    __syncthreads();
    uint32_t tmem;
    asm volatile("ld.shared.b32 %0, [%1];" : "=r"(tmem) : "r"(sb + 0));

    CLUSTER_ARRIVE();
    CLUSTER_WAIT();

    const int L = NLOC * NK_TC;                   // local k-iterations

    auto tma_pair = [&](int g, uint32_t stb, uint32_t mbar) {
        const int j = g >> 7, k = g & 127;
        const int t = cid + NCLUST * j;
        const int a_row = (t % M_TILES) * 256 + rank * 128;
        const int w_row = (t / M_TILES) * 256 + rank * 128;
        TMA_LOAD_3D_CG2(stb,          &tmx, 64 * k, a_row, 0, mbar);
        TMA_LOAD_3D_CG2(stb + SW_OFF, &tmw, 64 * k, w_row, 0, mbar);
    };

    if (wid == 0) {
        if (elect_one()) {
            if (rank == 0) {
                #pragma unroll
                for (int p = 0; p < 4; ++p) {
                    POLL_CHUNK(p);
                    MBARRIER_EXPECT_TX(FULL + p * 8, 2 * STG_TC);
                    tma_pair(p, sb + HDR_TC + p * STG_TC, FULL + p * 8);
                }
                for (int g = 0; g < L; ++g) {
                    const int tl = g >> 7, k = g & 127;
                    if (k == 0 && tl >= 2)
                        MBARRIER_WAIT_PARITY(EPI + (tl & 1) * 8, ((tl >> 1) - 1) & 1);
                    MBARRIER_WAIT_PARITY(FULL + (g % 5) * 8, (g / 5) & 1);
                    const uint32_t stb = sb + HDR_TC + (g % NSTAGE) * STG_TC;
                    const uint64_t dA  = MAKE_SMEM_DESC(stb);
                    const uint64_t dW  = MAKE_SMEM_DESC(stb + SW_OFF);
                    const uint32_t D   = tmem + (tl & 1) * 256;
                    const uint32_t first = (k == 0) ? 0u : 1u;
                    mma_f16_ss_cg2(D, dA + 0, dW + 0, IDESC_CG2, first);
                    mma_f16_ss_cg2(D, dA + 2, dW + 2, IDESC_CG2, 1u);
                    mma_f16_ss_cg2(D, dA + 0, dW + 4, IDESC_CG2, 1u);
                    mma_f16_ss_cg2(D, dA + 2, dW + 6, IDESC_CG2, 1u);
                    mma_f16_ss_cg2(D, dA + 4, dW + 0, IDESC_CG2, 1u);
                    mma_f16_ss_cg2(D, dA + 6, dW + 2, IDESC_CG2, 1u);
                    TCGEN05_COMMIT_MC_CG2(MBM + (g % 4) * 8);
                    if (k == 127) TCGEN05_COMMIT_MC_CG2(TILE + (tl & 1) * 8);
                    const int nxt = g + 4;
                    if (nxt < L) {
                        if (g >= 1) MBARRIER_WAIT_PARITY(MBM + ((g - 1) % 4) * 8, ((g - 1) / 4) & 1);
                        if (nxt < 128) POLL_CHUNK(nxt);
                        MBARRIER_EXPECT_TX(FULL + (nxt % 5) * 8, 2 * STG_TC);
                        tma_pair(nxt, sb + HDR_TC + (nxt % NSTAGE) * STG_TC, FULL + (nxt % 5) * 8);
                    }
                }
            } else {
                #pragma unroll
                for (int p = 0; p < 4; ++p) {
                    POLL_CHUNK(p);
                    tma_pair(p, sb + HDR_TC + p * STG_TC, FULL + p * 8);
                }
                for (int g = 0; g + 4 < L; ++g) {
                    if (g >= 1) MBARRIER_WAIT_PARITY(MBM + ((g - 1) % 4) * 8, ((g - 1) / 4) & 1);
                    const int nxt = g + 4;
                    if (nxt < 128) POLL_CHUNK(nxt);
                    tma_pair(nxt, sb + HDR_TC + (nxt % NSTAGE) * STG_TC, FULL + (nxt % 5) * 8);
                }
            }
        }
    } else {
        // ---- prep (warps 1-7 of all CTAs), overlapped with the pipeline ----
        prep_warp(lin * 7 + (wid - 1), (int)PREP_WARPS_TC, lane, x, W, U, s, V);
    }

    // consumers: warps 4-7 of both CTAs drain finished accumulators (after prep)
    if (wid >= 4) {
        const int sub = wid - 4;
        for (int tl = 0; tl < NLOC; ++tl) {
            MBARRIER_WAIT_PARITY(TILE + (tl & 1) * 8, (tl >> 1) & 1);
            TCGEN05_FENCE_AFTER();
            const int t = cid + NCLUST * tl;
            const int row = (t % M_TILES) * 256 + rank * 128 + sub * 32 + lane;
            const int n_b = (t / M_TILES) * 256;
            const uint32_t D = tmem + (tl & 1) * 256;
            #pragma unroll
            for (int cc = 0; cc < 8; ++cc) {
                uint32_t regs[32];
                TCGEN05_LD_X32(regs, D + cc * 32);
                TCGEN05_WAIT_LD();
                float* dst = out + (size_t)row * OUT_F + n_b + cc * 32;
                #pragma unroll
                for (int q = 0; q < 32; q += 4)
                    *reinterpret_cast<float4*>(dst + q) =
                        make_float4(__uint_as_float(regs[q]), __uint_as_float(regs[q + 1]),
                                    __uint_as_float(regs[q + 2]), __uint_as_float(regs[q + 3]));
            }
            TCGEN05_FENCE_BEFORE();
            asm volatile("bar.sync 1, 128;" ::: "memory");
            if (tid == 128) {
                if (rank == 0) MBARRIER_ARRIVE(EPI + (tl & 1) * 8);
                else           MBARRIER_ARRIVE_CLUSTER(EPI + (tl & 1) * 8, 0);
            }
        }
    }

    __syncthreads();
    CLUSTER_ARRIVE();
    CLUSTER_WAIT();
    if (wid == 0) {
        TCGEN05_RELQ_CG2();
        TCGEN05_DEALLOC_CG2(tmem, 512);
    }
    CLUSTER_ARRIVE();
    CLUSTER_WAIT();

#else
    // ============ fallback (mma.sync): self-prep + device barrier + tile loop ==
    prep_warp(lin * 8 + wid, (int)PREP_WARPS_FB, lane, x, W, U, s, V);
    __syncthreads();
    if (tid == 0) {
        __threadfence();
        atomicAdd(&g_cnt[128], 1u);
        unsigned v; const unsigned* c = &g_cnt[128];
        do { asm volatile("ld.acquire.gpu.u32 %0, [%1];" : "=r"(v) : "l"(c)); } while (v < 148u);
    }
    __syncthreads();

    const int wm = wid & 3;
    const int wn = wid >> 2;

    for (int tl = 0; tl < NLOC; ++tl) {
        const int t = cid + NCLUST * tl;
        const int mb  = (t % M_TILES) * 256 + rank * 128;
        const int n_b = (t / M_TILES) * 256;

        for (int nhalf = 0; nhalf < 2; ++nhalf) {
            const int n_base_fb = n_b + nhalf * 128;
            __syncthreads();

            auto issue = [&](int st, int kidx) {
                const uint32_t stb = sb + st * STG_FB;
                const int g = kidx;
                const int r0 = tid >> 2, c = tid & 3;
                #pragma unroll
                for (int j = 0; j < 2; ++j) {
                    int r = r0 + j * 64;
                    uint32_t rowoff = (uint32_t)(r * (ROWH * 2) + c * 16);
                    size_t bx = (size_t)(mb + r) * PK + (size_t)g * 64 + c * 8;
                    size_t bw = (size_t)(n_base_fb + r) * PK + (size_t)g * 64 + c * 8;
                    cp16(stb + AH_B + rowoff, &g_Xp[bx]);
                    cp16(stb + AL_B + rowoff, &g_Xp[bx + 32]);
                    cp16(stb + BH_B + rowoff, &g_Wp[bw]);
                    cp16(stb + BL_B + rowoff, &g_Wp[bw + 32]);
                }
            };

            issue(0, 0); CP_COMMIT();
            issue(1, 1); CP_COMMIT();

            float acc[2][8][4];
            #pragma unroll
            for (int a = 0; a < 2; ++a)
                #pragma unroll
                for (int b = 0; b < 8; ++b)
                    #pragma unroll
                    for (int cidx = 0; cidx < 4; ++cidx) acc[a][b][cidx] = 0.f;

            const int aRow  = wm * 32 + (lane & 15);
            const int aColH = (lane >> 4) * 8;
            const int bIdx  = lane & 7;
            const int bGrp  = lane >> 3;
            const int bRow  = wn * 64 + ((bGrp & 2) << 2) + bIdx;
            const int bColH = (bGrp & 1) * 8;

            for (int i = 0; i < NK_FB; ++i) {
                CP_WAIT(1);
                __syncthreads();
                if (i + 2 < NK_FB) issue((i + 2) % NSTAGE_FB, i + 2);
                CP_COMMIT();

                const uint32_t stb = sb + (i % NSTAGE_FB) * STG_FB;
                #pragma unroll
                for (int k16 = 0; k16 < 2; ++k16) {
                    uint32_t ah[2][4], al[2][4];
                    #pragma unroll
                    for (int mt = 0; mt < 2; ++mt) {
                        uint32_t off = (uint32_t)((aRow + mt * 16) * (ROWH * 2) +
                                                  (k16 * 16 + aColH) * 2);
                        ldm4(ah[mt], stb + AH_B + off);
                        ldm4(al[mt], stb + AL_B + off);
                    }
                    #pragma unroll
                    for (int j = 0; j < 4; ++j) {
                        uint32_t off = (uint32_t)((bRow + j * 16) * (ROWH * 2) +
                                                  (k16 * 16 + bColH) * 2);
                        uint32_t bh[4];
                        ldm4(bh, stb + BH_B + off);
                        #pragma unroll
                        for (int mt = 0; mt < 2; ++mt) {
                            mma16816(acc[mt][2 * j + 0], ah[mt], bh + 0);
                            mma16816(acc[mt][2 * j + 1], ah[mt], bh + 2);
                            mma16816(acc[mt][2 * j + 0], al[mt], bh + 0);
                            mma16816(acc[mt][2 * j + 1], al[mt], bh + 2);
                        }
                    }
                    #pragma unroll
                    for (int j = 0; j < 4; ++j) {
                        uint32_t off = (uint32_t)((bRow + j * 16) * (ROWH * 2) +
                                                  (k16 * 16 + bColH) * 2);
                        uint32_t bl[4];
                        ldm4(bl, stb + BL_B + off);
                        #pragma unroll
                        for (int mt = 0; mt < 2; ++mt) {
                            mma16816(acc[mt][2 * j + 0], ah[mt], bl + 0);
                            mma16816(acc[mt][2 * j + 1], ah[mt], bl + 2);
                        }
                    }
                }
            }

            #pragma unroll
            for (int mt = 0; mt < 2; ++mt) {
                const int row0 = mb + wm * 32 + mt * 16 + (lane >> 2);
                #pragma unroll
                for (int nb = 0; nb < 8; ++nb) {
                    const int col = n_base_fb + wn * 64 + nb * 8 + (lane & 3) * 2;
                    *reinterpret_cast<float2*>(out + (size_t)row0 * OUT_F + col) =
                        make_float2(acc[mt][nb][0], acc[mt][nb][1]);
                    *reinterpret_cast<float2*>(out + (size_t)(row0 + 8) * OUT_F + col) =
                        make_float2(acc[mt][nb][2], acc[mt][nb][3]);
                }
            }
        }
    }
#endif
}

// ===================== harness entry =====================
typedef CUresult (*PFN_encodeTiled_t)(
    CUtensorMap*, CUtensorMapDataType, cuuint32_t, void*,
    const cuuint64_t*, const cuuint64_t*, const cuuint32_t*, const cuuint32_t*,
    CUtensorMapInterleave, CUtensorMapSwizzle, CUtensorMapL2promotion,
    CUtensorMapFloatOOBfill);

extern "C" void kernel_launch(void* const* d_in, const int* in_sizes, int n_in,
                              void* d_out, int out_size)
{
    const float* x = (const float*)d_in[0];
    const float* W = (const float*)d_in[1];
    const float* U = (const float*)d_in[2];
    const float* s = (const float*)d_in[3];
    const float* V = (const float*)d_in[4];
    float* out = (float*)d_out;
    (void)in_sizes; (void)n_in; (void)out_size;

    // reset chunk-ready counters (graph-capturable, no allocation)
    void* pc = nullptr;
    cudaGetSymbolAddress(&pc, g_cnt);
    cudaMemsetAsync(pc, 0, sizeof(g_cnt));

    alignas(64) CUtensorMap tmx{}, tmw{};
    {
        void* px = nullptr; cudaGetSymbolAddress(&px, g_Xp);
        void* pw = nullptr; cudaGetSymbolAddress(&pw, g_Wp);
        PFN_encodeTiled_t enc = nullptr;
        cudaDriverEntryPointQueryResult st{};
        cudaGetDriverEntryPoint("cuTensorMapEncodeTiled", (void**)&enc,
                                cudaEnableDefault, &st);
        if (enc) {
            cuuint32_t box[3] = {64, 128, 1};
            cuuint32_t es[3]  = {1, 1, 1};
            cuuint64_t dimsX[3] = {(cuuint64_t)PK, (cuuint64_t)M_TOTAL, 1};
            cuuint64_t strX[2]  = {(cuuint64_t)PK * 2, (cuuint64_t)PK * 2 * M_TOTAL};
            enc(&tmx, CU_TENSOR_MAP_DATA_TYPE_BFLOAT16, 3, px, dimsX, strX, box, es,
                CU_TENSOR_MAP_INTERLEAVE_NONE, CU_TENSOR_MAP_SWIZZLE_128B,
                CU_TENSOR_MAP_L2_PROMOTION_L2_128B, CU_TENSOR_MAP_FLOAT_OOB_FILL_NONE);
            cuuint64_t dimsW[3] = {(cuuint64_t)PK, (cuuint64_t)OUT_F, 1};
            cuuint64_t strW[2]  = {(cuuint64_t)PK * 2, (cuuint64_t)PK * 2 * OUT_F};
            enc(&tmw, CU_TENSOR_MAP_DATA_TYPE_BFLOAT16, 3, pw, dimsW, strW, box, es,
                CU_TENSOR_MAP_INTERLEAVE_NONE, CU_TENSOR_MAP_SWIZZLE_128B,
                CU_TENSOR_MAP_L2_PROMOTION_L2_128B, CU_TENSOR_MAP_FLOAT_OOB_FILL_NONE);
        }
    }

    cudaFuncSetAttribute(gemm_kernel, cudaFuncAttributeMaxDynamicSharedMemorySize, SMEM_DYN);
    gemm_kernel<<<dim3(2, NCLUST, 1), THREADS, SMEM_DYN>>>(out, x, W, U, s, V, tmx, tmw);
}

// round 16
// speedup vs baseline: 1.0286x; 1.0286x over previous
#include <cuda_runtime.h>
#include <cuda.h>
#include <cuda_bf16.h>
#include <cstdint>
#include <cstddef>

// ===================== problem constants =====================
static constexpr int IN_F    = 4096;
static constexpr int OUT_F   = 4096;
static constexpr int RANK    = 16;
static constexpr int M_TOTAL = 4 * 2048;     // 8192 rows of x
static constexpr int PK      = 2 * IN_F;     // packed K (hi|lo per 32-group) = 8192

static constexpr int THREADS  = 256;
static constexpr int NCLUST   = 74;          // persistent clusters (148 CTAs)
static constexpr int NTILES   = (M_TOTAL / 256) * (OUT_F / 256);   // 512
static constexpr int M_TILES  = M_TOTAL / 256;                     // 32
static constexpr unsigned PREP_WARPS_TC = 148u * 7u;               // 1036
static constexpr unsigned PREP_WARPS_FB = 148u * 8u;               // 1184

// ---- tcgen05 cg2 path ----
static constexpr int KC_TC = 32;             // k-elems per stage
static constexpr int NK_TC = IN_F / KC_TC;   // 128 k-iters per tile
static constexpr int SW_OFF  = 16384;        // W slice offset within stage
static constexpr int STG_TC  = 32768;        // per-CTA stage bytes (X 16K + W 16K)
static constexpr int NSTAGE  = 5;
static constexpr int HDR_TC  = 1024;
static constexpr int SMEM_DYN = HDR_TC + NSTAGE * STG_TC;   // 164864

// idesc cg2 kind::f16: bf16 x bf16 -> f32, M=256, N=256, K-major both
static constexpr uint32_t IDESC_CG2 =
    (1u << 4) | (1u << 7) | (1u << 10) | ((256 / 8u) << 17) | ((256 / 16u) << 24);

// ---- fallback (mma.sync) ----
static constexpr int KC_FB = 32;
static constexpr int NK_FB = IN_F / KC_FB;   // 128
static constexpr int ROWH  = 40;
static constexpr int AH_B  = 0;
static constexpr int AL_B  = 128 * ROWH * 2;
static constexpr int BH_B  = 2 * 128 * ROWH * 2;
static constexpr int BL_B  = 3 * 128 * ROWH * 2;
static constexpr int STG_FB = 4 * 128 * ROWH * 2;    // 40960
static constexpr int NSTAGE_FB = 3;

// ===================== scratch (__device__ globals; no cudaMalloc) ===========
__device__ __nv_bfloat16 g_Xp[(size_t)M_TOTAL * PK];   // 128 MB
__device__ __nv_bfloat16 g_Wp[(size_t)OUT_F * PK];     // 64 MB
__device__ unsigned g_cnt[132];   // [0..127] chunk-ready counters, [128] fb barrier

// ===================== common helpers =====================
__device__ __forceinline__ uint32_t smem_u32(const void* p) {
    uint32_t a;
    asm("{ .reg .u64 t; cvta.to.shared.u64 t, %1; cvt.u32.u64 %0, t; }" : "=r"(a) : "l"(p));
    return a;
}
__device__ __forceinline__ void cp16(uint32_t sdst, const void* gsrc) {
    asm volatile("cp.async.cg.shared.global [%0], [%1], 16;" :: "r"(sdst), "l"(gsrc));
}
#define CP_COMMIT() asm volatile("cp.async.commit_group;" ::: "memory")
#define CP_WAIT(n)  asm volatile("cp.async.wait_group %0;" :: "n"(n) : "memory")

// ===================== fused prep (runs inside gemm kernel) ==================
// k-chunk-major; per chunk each warp handles up to 8 X rows and 4 W rows, with
// all global loads issued back-to-back (MLP 8 / MLP 8) before any conversion.
// Guards are warp-uniform, so __shfl_sync stays converged.
__device__ __forceinline__ void prep_warp(
    int gw, int nwarps, int lane,
    const float* __restrict__ x, const float* __restrict__ W,
    const float* __restrict__ U, const float* __restrict__ s,
    const float* __restrict__ V)
{
    const float s_l = (lane < 16) ? s[lane] : 0.f;
    for (int k = 0; k < 128; ++k) {
        const int col = k * 32 + lane;

        // ---- X: up to 8 rows, loads batched (MLP 8) ----
        {
            float f[8];
            int   rows[8];
            bool  ok[8];
            #pragma unroll
            for (int j = 0; j < 8; ++j) {
                rows[j] = gw + j * nwarps;
                ok[j]   = rows[j] < M_TOTAL;           // warp-uniform
                f[j]    = ok[j] ? x[(size_t)rows[j] * IN_F + col] : 0.f;
            }
            #pragma unroll
            for (int j = 0; j < 8; ++j) {
                if (ok[j]) {
                    __nv_bfloat16 hb = __float2bfloat16(f[j]);
                    float res = f[j] - __bfloat162float(hb);
                    __nv_bfloat16 lb = __float2bfloat16(res);
                    size_t base = (size_t)rows[j] * PK + (size_t)k * 64 + lane;
                    g_Xp[base]      = hb;
                    g_Xp[base + 32] = lb;
                }
            }
        }

        // ---- V block for this chunk: lane holds V[k*32+lane][0..15] ----
        float v[16];
        {
            const float4* vp = reinterpret_cast<const float4*>(
                V + (size_t)(k * 32 + lane) * RANK);
            float4 a0 = vp[0], a1 = vp[1], a2 = vp[2], a3 = vp[3];
            v[0]=a0.x; v[1]=a0.y; v[2]=a0.z; v[3]=a0.w;
            v[4]=a1.x; v[5]=a1.y; v[6]=a1.z; v[7]=a1.w;
            v[8]=a2.x; v[9]=a2.y; v[10]=a2.z; v[11]=a2.w;
            v[12]=a3.x; v[13]=a3.y; v[14]=a3.z; v[15]=a3.w;
        }

        // ---- W': up to 4 rows, W+U loads batched (MLP 8) ----
        {
            float w[4], u[4];
            int   rows[4];
            bool  ok[4];
            #pragma unroll
            for (int j = 0; j < 4; ++j) {
                rows[j] = gw + j * nwarps;
                ok[j]   = rows[j] < OUT_F;             // warp-uniform
                w[j]    = ok[j] ? W[(size_t)rows[j] * IN_F + col] : 0.f;
                u[j]    = (ok[j] && lane < 16)
                          ? U[(size_t)rows[j] * RANK + lane] * s_l : 0.f;
            }
            #pragma unroll
            for (int j = 0; j < 4; ++j) {
                if (ok[j]) {                            // warp-uniform
                    float acc = w[j];
                    #pragma unroll
                    for (int r = 0; r < 16; ++r)
                        acc += __shfl_sync(0xFFFFFFFFu, u[j], r) * v[r];
                    __nv_bfloat16 hb = __float2bfloat16(acc);
                    float res = acc - __bfloat162float(hb);
                    __nv_bfloat16 lb = __float2bfloat16(res);
                    size_t base = (size_t)rows[j] * PK + (size_t)k * 64 + lane;
                    g_Wp[base]      = hb;
                    g_Wp[base + 32] = lb;
                }
            }
        }

        __threadfence();
        __syncwarp();
        if (lane == 0) atomicAdd(&g_cnt[k], 1u);
    }
}

// ===================== tcgen05/TMA machinery (sm_103a cubin only) =============
#if defined(__CUDA_ARCH_FEAT_SM103_ALL)
__device__ __forceinline__ uint32_t elect_one() {
    uint32_t p;
    asm volatile("{\n\t.reg .pred p;\n\telect.sync _|p, 0xFFFFFFFF;\n\tselp.b32 %0, 1, 0, p;\n\t}"
                 : "=r"(p));
    return p;
}
#define MBARRIER_INIT(addr, cnt) \
    asm volatile("mbarrier.init.shared.b64 [%0], %1;" :: "r"(addr), "r"(cnt) : "memory")
#define MBARRIER_ARRIVE(mbar) \
    asm volatile("mbarrier.arrive.shared.b64 _, [%0];" :: "r"((uint32_t)(mbar)) : "memory")
#define MBARRIER_ARRIVE_CLUSTER(mbar, trank) \
    asm volatile("{\n\t.reg .b32 ra;\n\t" \
                 "mapa.shared::cluster.u32 ra, %0, %1;\n\t" \
                 "mbarrier.arrive.shared::cluster.b64 _, [ra];\n\t}" \
                 :: "r"((uint32_t)(mbar)), "r"((uint32_t)(trank)) : "memory")
#define MBARRIER_EXPECT_TX(mbar, bytes) \
    asm volatile("mbarrier.arrive.expect_tx.shared.b64 _, [%0], %1;" \
                 :: "r"((uint32_t)(mbar)), "r"((uint32_t)(bytes)) : "memory")
#define MBARRIER_WAIT_PARITY(mbar, par) do {                                             \
    uint32_t _m = (uint32_t)(mbar); uint32_t _p = (uint32_t)(par); uint32_t _d;          \
    asm volatile("{\n\t.reg .pred p;\n\t"                                                \
        "mbarrier.try_wait.parity.acquire.cta.shared::cta.b64 p, [%1], %2;\n\t"          \
        "selp.b32 %0, 1, 0, p;\n\t}" : "=r"(_d) : "r"(_m), "r"(_p) : "memory");          \
    if (!_d) {                                                                           \
        asm volatile("{\n\t.reg .pred P1;\n\tWL_%=: \n\t"                                \
            "mbarrier.try_wait.parity.acquire.cta.shared::cta.b64 P1, [%0], %1, 0x989680;\n\t" \
            "@P1 bra.uni WD_%=;\n\tbra.uni WL_%=;\n\tWD_%=: \n\t}"                       \
            :: "r"(_m), "r"(_p) : "memory");                                             \
    }                                                                                    \
} while (0)
#define TMA_LOAD_3D_CG2(smem_addr, tmap, c0, c1, c2, mbar) \
    asm volatile( \
        "{\n\t.reg .b32 lb;\n\t" \
        "and.b32 lb, %5, 0xFEFFFFFF;\n\t" \
        "cp.async.bulk.tensor.3d.cta_group::2.shared::cluster.global" \
        ".tile.mbarrier::complete_tx::bytes " \
        "[%0], [%1, {%2, %3, %4}], [lb];\n\t}" \
        :: "r"((uint32_t)(smem_addr)), "l"(tmap), \
           "r"((int)(c0)), "r"((int)(c1)), "r"((int)(c2)), \
           "r"((uint32_t)(mbar)) : "memory")
#define TCGEN05_ALLOC_CG2(sa, n) \
    asm volatile("tcgen05.alloc.cta_group::2.sync.aligned.shared::cta.b32 [%0], %1;" \
                 :: "r"((uint32_t)(sa)), "r"((uint32_t)(n)) : "memory")
#define TCGEN05_RELQ_CG2() \
    asm volatile("tcgen05.relinquish_alloc_permit.cta_group::2.sync.aligned;")
#define TCGEN05_DEALLOC_CG2(t, n) \
    asm volatile("tcgen05.dealloc.cta_group::2.sync.aligned.b32 %0, %1;" \
                 :: "r"(t), "r"((uint32_t)(n)))
#define TCGEN05_COMMIT_MC_CG2(mb) \
    asm volatile("tcgen05.commit.cta_group::2.mbarrier::arrive::one.shared::cluster.multicast::cluster.b64 [%0], %1;" \
                 :: "r"((uint32_t)(mb)), "h"((uint16_t)3) : "memory")
#define TCGEN05_FENCE_AFTER()  asm volatile("tcgen05.fence::after_thread_sync;" ::: "memory")
#define TCGEN05_FENCE_BEFORE() asm volatile("tcgen05.fence::before_thread_sync;" ::: "memory")
#define TCGEN05_WAIT_LD()      asm volatile("tcgen05.wait::ld.sync.aligned;" ::: "memory")
#define CLUSTER_ARRIVE() asm volatile("barrier.cluster.arrive.aligned;" ::: "memory")
#define CLUSTER_WAIT()   asm volatile("barrier.cluster.wait.aligned;" ::: "memory")

// poll a prep chunk counter (only used during tile 0), then fence to async proxy
#define POLL_CHUNK(kk) do {                                                   \
    unsigned _v; const unsigned* _c = &g_cnt[(kk)];                           \
    while (true) {                                                            \
        asm volatile("ld.acquire.gpu.u32 %0, [%1];" : "=r"(_v) : "l"(_c));    \
        if (_v >= PREP_WARPS_TC) break;                                       \
        asm volatile("nanosleep.u32 128;");                                   \
    }                                                                         \
    asm volatile("fence.proxy.async;" ::: "memory");                          \
} while (0)

#define TCGEN05_LD_X32(r, ta) \
    asm volatile( \
        "tcgen05.ld.sync.aligned.32x32b.x32.b32 " \
        "{%0, %1, %2, %3, %4, %5, %6, %7, " \
        " %8, %9, %10, %11, %12, %13, %14, %15, " \
        " %16, %17, %18, %19, %20, %21, %22, %23, " \
        " %24, %25, %26, %27, %28, %29, %30, %31}, [%32];" \
        : "=r"((r)[0]),  "=r"((r)[1]),  "=r"((r)[2]),  "=r"((r)[3]), \
          "=r"((r)[4]),  "=r"((r)[5]),  "=r"((r)[6]),  "=r"((r)[7]), \
          "=r"((r)[8]),  "=r"((r)[9]),  "=r"((r)[10]), "=r"((r)[11]), \
          "=r"((r)[12]), "=r"((r)[13]), "=r"((r)[14]), "=r"((r)[15]), \
          "=r"((r)[16]), "=r"((r)[17]), "=r"((r)[18]), "=r"((r)[19]), \
          "=r"((r)[20]), "=r"((r)[21]), "=r"((r)[22]), "=r"((r)[23]), \
          "=r"((r)[24]), "=r"((r)[25]), "=r"((r)[26]), "=r"((r)[27]), \
          "=r"((r)[28]), "=r"((r)[29]), "=r"((r)[30]), "=r"((r)[31]) \
        : "r"(ta))

static constexpr uint64_t SMEM_DESC_BASE_SW128 =
    (uint64_t(2) << 61) | (uint64_t(1) << 46) | (uint64_t(64) << 32) | (uint64_t(1) << 16);
#define MAKE_SMEM_DESC(ba) (SMEM_DESC_BASE_SW128 | ((uint64_t)((ba) >> 4) & 0x3FFF))

__device__ __forceinline__ void mma_f16_ss_cg2(uint32_t d, uint64_t a, uint64_t b,
                                               uint32_t idesc, uint32_t acc) {
    asm volatile(
        "{\n\t.reg .pred p;\n\tsetp.ne.u32 p, %4, 0;\n\t"
        "tcgen05.mma.cta_group::2.kind::f16 [%0], %1, %2, %3, "
        "{%5, %5, %5, %5, %5, %5, %5, %5}, p;\n\t}"
        :: "r"(d), "l"(a), "l"(b), "r"(idesc), "r"(acc), "r"(0u) : "memory");
}
#else
__device__ __forceinline__ void ldm4(uint32_t* r, uint32_t addr) {
    asm volatile("ldmatrix.sync.aligned.m8n8.x4.shared.b16 {%0,%1,%2,%3}, [%4];"
                 : "=r"(r[0]), "=r"(r[1]), "=r"(r[2]), "=r"(r[3]) : "r"(addr));
}
__device__ __forceinline__ void mma16816(float* d, const uint32_t* a, const uint32_t* b) {
    asm volatile(
        "mma.sync.aligned.m16n8k16.row.col.f32.bf16.bf16.f32 "
        "{%0,%1,%2,%3}, {%4,%5,%6,%7}, {%8,%9}, {%0,%1,%2,%3};"
        : "+f"(d[0]), "+f"(d[1]), "+f"(d[2]), "+f"(d[3])
        : "r"(a[0]), "r"(a[1]), "r"(a[2]), "r"(a[3]), "r"(b[0]), "r"(b[1]));
}
#endif

// ===================== fused persistent kernel =====================
// grid (2, 74, 1), cluster (2,1,1), 256 threads.
// warp 0: MMA/TMA pipeline (rank0) / TMA producer (rank1)
// warps 1-3: prep only; warps 4-7: prep, then epilogue
__global__ void __launch_bounds__(THREADS, 1) __cluster_dims__(2, 1, 1)
gemm_kernel(float* __restrict__ out,
            const float* __restrict__ x, const float* __restrict__ W,
            const float* __restrict__ U, const float* __restrict__ s,
            const float* __restrict__ V,
            const __grid_constant__ CUtensorMap tmx,
            const __grid_constant__ CUtensorMap tmw)
{
    extern __shared__ char smem[];
    const uint32_t sb = smem_u32(smem);
    const int tid  = threadIdx.x;
    const int lane = tid & 31;
    const int wid  = tid >> 5;
    const int rank = (int)blockIdx.x;
    const int cid  = (int)blockIdx.y;             // cluster id 0..73
    const int lin  = rank + 2 * cid;              // linear CTA id 0..147
    const int NLOC = (NTILES - 1 - cid) / NCLUST + 1;   // 6 or 7 local tiles

#if defined(__CUDA_ARCH_FEAT_SM103_ALL)
    const uint32_t FULL = sb + 64;    // 5 slots
    const uint32_t MBM  = sb + 128;   // 4 slots
    const uint32_t TILE = sb + 192;   // 2 slots (tile-done, multicast)
    const uint32_t EPI  = sb + 256;   // 2 slots (buffer free, count 2, on rank0)

    if (tid == 0) {
        for (int i = 0; i < 5; ++i) MBARRIER_INIT(FULL + i * 8, 1);
        for (int i = 0; i < 4; ++i) MBARRIER_INIT(MBM + i * 8, 1);
        for (int i = 0; i < 2; ++i) MBARRIER_INIT(TILE + i * 8, 1);
        for (int i = 0; i < 2; ++i) MBARRIER_INIT(EPI + i * 8, 2);
    }
    if (wid == 0) TCGEN05_ALLOC_CG2(sb + 0, 512);   // two 256-col accumulators
    __syncthreads();
    uint32_t tmem;
    asm volatile("ld.shared.b32 %0, [%1];" : "=r"(tmem) : "r"(sb + 0));

    CLUSTER_ARRIVE();
    CLUSTER_WAIT();

    const int L = NLOC * NK_TC;                   // local k-iterations

    auto tma_pair = [&](int g, uint32_t stb, uint32_t mbar) {
        const int j = g >> 7, k = g & 127;
        const int t = cid + NCLUST * j;
        const int a_row = (t % M_TILES) * 256 + rank * 128;
        const int w_row = (t / M_TILES) * 256 + rank * 128;
        TMA_LOAD_3D_CG2(stb,          &tmx, 64 * k, a_row, 0, mbar);
        TMA_LOAD_3D_CG2(stb + SW_OFF, &tmw, 64 * k, w_row, 0, mbar);
    };

    if (wid == 0) {
        if (elect_one()) {
            if (rank == 0) {
                #pragma unroll
                for (int p = 0; p < 4; ++p) {
                    POLL_CHUNK(p);
                    MBARRIER_EXPECT_TX(FULL + p * 8, 2 * STG_TC);
                    tma_pair(p, sb + HDR_TC + p * STG_TC, FULL + p * 8);
                }
                for (int g = 0; g < L; ++g) {
                    const int tl = g >> 7, k = g & 127;
                    if (k == 0 && tl >= 2)
                        MBARRIER_WAIT_PARITY(EPI + (tl & 1) * 8, ((tl >> 1) - 1) & 1);
                    MBARRIER_WAIT_PARITY(FULL + (g % 5) * 8, (g / 5) & 1);
                    const uint32_t stb = sb + HDR_TC + (g % NSTAGE) * STG_TC;
                    const uint64_t dA  = MAKE_SMEM_DESC(stb);
                    const uint64_t dW  = MAKE_SMEM_DESC(stb + SW_OFF);
                    const uint32_t D   = tmem + (tl & 1) * 256;
                    const uint32_t first = (k == 0) ? 0u : 1u;
                    mma_f16_ss_cg2(D, dA + 0, dW + 0, IDESC_CG2, first);
                    mma_f16_ss_cg2(D, dA + 2, dW + 2, IDESC_CG2, 1u);
                    mma_f16_ss_cg2(D, dA + 0, dW + 4, IDESC_CG2, 1u);
                    mma_f16_ss_cg2(D, dA + 2, dW + 6, IDESC_CG2, 1u);
                    mma_f16_ss_cg2(D, dA + 4, dW + 0, IDESC_CG2, 1u);
                    mma_f16_ss_cg2(D, dA + 6, dW + 2, IDESC_CG2, 1u);
                    TCGEN05_COMMIT_MC_CG2(MBM + (g % 4) * 8);
                    if (k == 127) TCGEN05_COMMIT_MC_CG2(TILE + (tl & 1) * 8);
                    const int nxt = g + 4;
                    if (nxt < L) {
                        if (g >= 1) MBARRIER_WAIT_PARITY(MBM + ((g - 1) % 4) * 8, ((g - 1) / 4) & 1);
                        if (nxt < 128) POLL_CHUNK(nxt);
                        MBARRIER_EXPECT_TX(FULL + (nxt % 5) * 8, 2 * STG_TC);
                        tma_pair(nxt, sb + HDR_TC + (nxt % NSTAGE) * STG_TC, FULL + (nxt % 5) * 8);
                    }
                }
            } else {
                #pragma unroll
                for (int p = 0; p < 4; ++p) {
                    POLL_CHUNK(p);
                    tma_pair(p, sb + HDR_TC + p * STG_TC, FULL + p * 8);
                }
                for (int g = 0; g + 4 < L; ++g) {
                    if (g >= 1) MBARRIER_WAIT_PARITY(MBM + ((g - 1) % 4) * 8, ((g - 1) / 4) & 1);
                    const int nxt = g + 4;
                    if (nxt < 128) POLL_CHUNK(nxt);
                    tma_pair(nxt, sb + HDR_TC + (nxt % NSTAGE) * STG_TC, FULL + (nxt % 5) * 8);
                }
            }
        }
    } else {
        // ---- prep (warps 1-7 of all CTAs), overlapped with the pipeline ----
        prep_warp(lin * 7 + (wid - 1), (int)PREP_WARPS_TC, lane, x, W, U, s, V);
    }

    // consumers: warps 4-7 of both CTAs drain finished accumulators (after prep)
    if (wid >= 4) {
        const int sub = wid - 4;
        for (int tl = 0; tl < NLOC; ++tl) {
            MBARRIER_WAIT_PARITY(TILE + (tl & 1) * 8, (tl >> 1) & 1);
            TCGEN05_FENCE_AFTER();
            const int t = cid + NCLUST * tl;
            const int row = (t % M_TILES) * 256 + rank * 128 + sub * 32 + lane;
            const int n_b = (t / M_TILES) * 256;
            const uint32_t D = tmem + (tl & 1) * 256;
            #pragma unroll
            for (int cc = 0; cc < 8; ++cc) {
                uint32_t regs[32];
                TCGEN05_LD_X32(regs, D + cc * 32);
                TCGEN05_WAIT_LD();
                float* dst = out + (size_t)row * OUT_F + n_b + cc * 32;
                #pragma unroll
                for (int q = 0; q < 32; q += 4)
                    *reinterpret_cast<float4*>(dst + q) =
                        make_float4(__uint_as_float(regs[q]), __uint_as_float(regs[q + 1]),
                                    __uint_as_float(regs[q + 2]), __uint_as_float(regs[q + 3]));
            }
            TCGEN05_FENCE_BEFORE();
            asm volatile("bar.sync 1, 128;" ::: "memory");
            if (tid == 128) {
                if (rank == 0) MBARRIER_ARRIVE(EPI + (tl & 1) * 8);
                else           MBARRIER_ARRIVE_CLUSTER(EPI + (tl & 1) * 8, 0);
            }
        }
    }

    __syncthreads();
    CLUSTER_ARRIVE();
    CLUSTER_WAIT();
    if (wid == 0) {
        TCGEN05_RELQ_CG2();
        TCGEN05_DEALLOC_CG2(tmem, 512);
    }
    CLUSTER_ARRIVE();
    CLUSTER_WAIT();

#else
    // ============ fallback (mma.sync): self-prep + device barrier + tile loop ==
    prep_warp(lin * 8 + wid, (int)PREP_WARPS_FB, lane, x, W, U, s, V);
    __syncthreads();
    if (tid == 0) {
        __threadfence();
        atomicAdd(&g_cnt[128], 1u);
        unsigned v; const unsigned* c = &g_cnt[128];
        do { asm volatile("ld.acquire.gpu.u32 %0, [%1];" : "=r"(v) : "l"(c)); } while (v < 148u);
    }
    __syncthreads();

    const int wm = wid & 3;
    const int wn = wid >> 2;

    for (int tl = 0; tl < NLOC; ++tl) {
        const int t = cid + NCLUST * tl;
        const int mb  = (t % M_TILES) * 256 + rank * 128;
        const int n_b = (t / M_TILES) * 256;

        for (int nhalf = 0; nhalf < 2; ++nhalf) {
            const int n_base_fb = n_b + nhalf * 128;
            __syncthreads();

            auto issue = [&](int st, int kidx) {
                const uint32_t stb = sb + st * STG_FB;
                const int g = kidx;
                const int r0 = tid >> 2, c = tid & 3;
                #pragma unroll
                for (int j = 0; j < 2; ++j) {
                    int r = r0 + j * 64;
                    uint32_t rowoff = (uint32_t)(r * (ROWH * 2) + c * 16);
                    size_t bx = (size_t)(mb + r) * PK + (size_t)g * 64 + c * 8;
                    size_t bw = (size_t)(n_base_fb + r) * PK + (size_t)g * 64 + c * 8;
                    cp16(stb + AH_B + rowoff, &g_Xp[bx]);
                    cp16(stb + AL_B + rowoff, &g_Xp[bx + 32]);
                    cp16(stb + BH_B + rowoff, &g_Wp[bw]);
                    cp16(stb + BL_B + rowoff, &g_Wp[bw + 32]);
                }
            };

            issue(0, 0); CP_COMMIT();
            issue(1, 1); CP_COMMIT();

            float acc[2][8][4];
            #pragma unroll
            for (int a = 0; a < 2; ++a)
                #pragma unroll
                for (int b = 0; b < 8; ++b)
                    #pragma unroll
                    for (int cidx = 0; cidx < 4; ++cidx) acc[a][b][cidx] = 0.f;

            const int aRow  = wm * 32 + (lane & 15);
            const int aColH = (lane >> 4) * 8;
            const int bIdx  = lane & 7;
            const int bGrp  = lane >> 3;
            const int bRow  = wn * 64 + ((bGrp & 2) << 2) + bIdx;
            const int bColH = (bGrp & 1) * 8;

            for (int i = 0; i < NK_FB; ++i) {
                CP_WAIT(1);
                __syncthreads();
                if (i + 2 < NK_FB) issue((i + 2) % NSTAGE_FB, i + 2);
                CP_COMMIT();

                const uint32_t stb = sb + (i % NSTAGE_FB) * STG_FB;
                #pragma unroll
                for (int k16 = 0; k16 < 2; ++k16) {
                    uint32_t ah[2][4], al[2][4];
                    #pragma unroll
                    for (int mt = 0; mt < 2; ++mt) {
                        uint32_t off = (uint32_t)((aRow + mt * 16) * (ROWH * 2) +
                                                  (k16 * 16 + aColH) * 2);
                        ldm4(ah[mt], stb + AH_B + off);
                        ldm4(al[mt], stb + AL_B + off);
                    }
                    #pragma unroll
                    for (int j = 0; j < 4; ++j) {
                        uint32_t off = (uint32_t)((bRow + j * 16) * (ROWH * 2) +
                                                  (k16 * 16 + bColH) * 2);
                        uint32_t bh[4];
                        ldm4(bh, stb + BH_B + off);
                        #pragma unroll
                        for (int mt = 0; mt < 2; ++mt) {
                            mma16816(acc[mt][2 * j + 0], ah[mt], bh + 0);
                            mma16816(acc[mt][2 * j + 1], ah[mt], bh + 2);
                            mma16816(acc[mt][2 * j + 0], al[mt], bh + 0);
                            mma16816(acc[mt][2 * j + 1], al[mt], bh + 2);
                        }
                    }
                    #pragma unroll
                    for (int j = 0; j < 4; ++j) {
                        uint32_t off = (uint32_t)((bRow + j * 16) * (ROWH * 2) +
                                                  (k16 * 16 + bColH) * 2);
                        uint32_t bl[4];
                        ldm4(bl, stb + BL_B + off);
                        #pragma unroll
                        for (int mt = 0; mt < 2; ++mt) {
                            mma16816(acc[mt][2 * j + 0], ah[mt], bl + 0);
                            mma16816(acc[mt][2 * j + 1], ah[mt], bl + 2);
                        }
                    }
                }
            }

            #pragma unroll
            for (int mt = 0; mt < 2; ++mt) {
                const int row0 = mb + wm * 32 + mt * 16 + (lane >> 2);
                #pragma unroll
                for (int nb = 0; nb < 8; ++nb) {
                    const int col = n_base_fb + wn * 64 + nb * 8 + (lane & 3) * 2;
                    *reinterpret_cast<float2*>(out + (size_t)row0 * OUT_F + col) =
                        make_float2(acc[mt][nb][0], acc[mt][nb][1]);
                    *reinterpret_cast<float2*>(out + (size_t)(row0 + 8) * OUT_F + col) =
                        make_float2(acc[mt][nb][2], acc[mt][nb][3]);
                }
            }
        }
    }
#endif
}

// ===================== harness entry =====================
typedef CUresult (*PFN_encodeTiled_t)(
    CUtensorMap*, CUtensorMapDataType, cuuint32_t, void*,
    const cuuint64_t*, const cuuint64_t*, const cuuint32_t*, const cuuint32_t*,
    CUtensorMapInterleave, CUtensorMapSwizzle, CUtensorMapL2promotion,
    CUtensorMapFloatOOBfill);

extern "C" void kernel_launch(void* const* d_in, const int* in_sizes, int n_in,
                              void* d_out, int out_size)
{
    const float* x = (const float*)d_in[0];
    const float* W = (const float*)d_in[1];
    const float* U = (const float*)d_in[2];
    const float* s = (const float*)d_in[3];
    const float* V = (const float*)d_in[4];
    float* out = (float*)d_out;
    (void)in_sizes; (void)n_in; (void)out_size;

    // reset chunk-ready counters (graph-capturable, no allocation)
    void* pc = nullptr;
    cudaGetSymbolAddress(&pc, g_cnt);
    cudaMemsetAsync(pc, 0, sizeof(g_cnt));

    alignas(64) CUtensorMap tmx{}, tmw{};
    {
        void* px = nullptr; cudaGetSymbolAddress(&px, g_Xp);
        void* pw = nullptr; cudaGetSymbolAddress(&pw, g_Wp);
        PFN_encodeTiled_t enc = nullptr;
        cudaDriverEntryPointQueryResult st{};
        cudaGetDriverEntryPoint("cuTensorMapEncodeTiled", (void**)&enc,
                                cudaEnableDefault, &st);
        if (enc) {
            cuuint32_t box[3] = {64, 128, 1};
            cuuint32_t es[3]  = {1, 1, 1};
            cuuint64_t dimsX[3] = {(cuuint64_t)PK, (cuuint64_t)M_TOTAL, 1};
            cuuint64_t strX[2]  = {(cuuint64_t)PK * 2, (cuuint64_t)PK * 2 * M_TOTAL};
            enc(&tmx, CU_TENSOR_MAP_DATA_TYPE_BFLOAT16, 3, px, dimsX, strX, box, es,
                CU_TENSOR_MAP_INTERLEAVE_NONE, CU_TENSOR_MAP_SWIZZLE_128B,
                CU_TENSOR_MAP_L2_PROMOTION_L2_128B, CU_TENSOR_MAP_FLOAT_OOB_FILL_NONE);
            cuuint64_t dimsW[3] = {(cuuint64_t)PK, (cuuint64_t)OUT_F, 1};
            cuuint64_t strW[2]  = {(cuuint64_t)PK * 2, (cuuint64_t)PK * 2 * OUT_F};
            enc(&tmw, CU_TENSOR_MAP_DATA_TYPE_BFLOAT16, 3, pw, dimsW, strW, box, es,
                CU_TENSOR_MAP_INTERLEAVE_NONE, CU_TENSOR_MAP_SWIZZLE_128B,
                CU_TENSOR_MAP_L2_PROMOTION_L2_128B, CU_TENSOR_MAP_FLOAT_OOB_FILL_NONE);
        }
    }

    cudaFuncSetAttribute(gemm_kernel, cudaFuncAttributeMaxDynamicSharedMemorySize, SMEM_DYN);
    gemm_kernel<<<dim3(2, NCLUST, 1), THREADS, SMEM_DYN>>>(out, x, W, U, s, V, tmx, tmw);
}

// round 17
// speedup vs baseline: 1.0391x; 1.0103x over previous
#include <cuda_runtime.h>
#include <cuda.h>
#include <cuda_bf16.h>
#include <cstdint>
#include <cstddef>

// ===================== problem constants =====================
static constexpr int IN_F    = 4096;
static constexpr int OUT_F   = 4096;
static constexpr int RANK    = 16;
static constexpr int M_TOTAL = 4 * 2048;     // 8192 rows of x
static constexpr int PK      = 2 * IN_F;     // packed K (hi|lo per 32-group) = 8192

static constexpr int THREADS  = 256;
static constexpr int NCLUST   = 74;          // persistent clusters (148 CTAs)
static constexpr int NTILES   = (M_TOTAL / 256) * (OUT_F / 256);   // 512
static constexpr int M_TILES  = M_TOTAL / 256;                     // 32
static constexpr unsigned PREP_CTAS = 148u;  // one arrive per CTA per chunk

// ---- tcgen05 cg2 path ----
static constexpr int KC_TC = 32;             // k-elems per stage
static constexpr int NK_TC = IN_F / KC_TC;   // 128 k-iters per tile
static constexpr int SW_OFF  = 16384;        // W slice offset within stage
static constexpr int STG_TC  = 32768;        // per-CTA stage bytes (X 16K + W 16K)
static constexpr int NSTAGE  = 5;
static constexpr int HDR_TC  = 1024;
static constexpr int SMEM_DYN = HDR_TC + NSTAGE * STG_TC;   // 164864

// idesc cg2 kind::f16: bf16 x bf16 -> f32, M=256, N=256, K-major both
static constexpr uint32_t IDESC_CG2 =
    (1u << 4) | (1u << 7) | (1u << 10) | ((256 / 8u) << 17) | ((256 / 16u) << 24);

// ---- fallback (mma.sync) ----
static constexpr int KC_FB = 32;
static constexpr int NK_FB = IN_F / KC_FB;   // 128
static constexpr int ROWH  = 40;
static constexpr int AH_B  = 0;
static constexpr int AL_B  = 128 * ROWH * 2;
static constexpr int BH_B  = 2 * 128 * ROWH * 2;
static constexpr int BL_B  = 3 * 128 * ROWH * 2;
static constexpr int STG_FB = 4 * 128 * ROWH * 2;    // 40960
static constexpr int NSTAGE_FB = 3;

// ===================== scratch (__device__ globals; no cudaMalloc) ===========
__device__ __nv_bfloat16 g_Xp[(size_t)M_TOTAL * PK];   // 128 MB
__device__ __nv_bfloat16 g_Wp[(size_t)OUT_F * PK];     // 64 MB
// chunk-ready counters, PADDED to 128B stride (atomic line-contention fix).
// counter k at g_cnt[k*32]; fallback device-barrier at g_cnt[128*32].
__device__ unsigned g_cnt[128 * 32 + 32];

// ===================== common helpers =====================
__device__ __forceinline__ uint32_t smem_u32(const void* p) {
    uint32_t a;
    asm("{ .reg .u64 t; cvta.to.shared.u64 t, %1; cvt.u32.u64 %0, t; }" : "=r"(a) : "l"(p));
    return a;
}
__device__ __forceinline__ void cp16(uint32_t sdst, const void* gsrc) {
    asm volatile("cp.async.cg.shared.global [%0], [%1], 16;" :: "r"(sdst), "l"(gsrc));
}
#define CP_COMMIT() asm volatile("cp.async.commit_group;" ::: "memory")
#define CP_WAIT(n)  asm volatile("cp.async.wait_group %0;" :: "n"(n) : "memory")

// ===================== fused prep (runs inside gemm kernel) ==================
// k-chunk-major; per chunk each warp handles up to 8 X rows and 4 W rows with
// batched loads (MLP 8). Per chunk: named-barrier across the prep warps of this
// CTA, then ONE thread fences + atomics the padded counter (148 arrivals/chunk
// chip-wide instead of 1036; counters on distinct 128B lines).
__device__ __forceinline__ void prep_warp(
    int gw, int nwarps, int lane, int tid, int arrive_tid, unsigned bar_cnt,
    const float* __restrict__ x, const float* __restrict__ W,
    const float* __restrict__ U, const float* __restrict__ s,
    const float* __restrict__ V)
{
    const float s_l = (lane < 16) ? s[lane] : 0.f;
    for (int k = 0; k < 128; ++k) {
        const int col = k * 32 + lane;

        // ---- X: up to 8 rows, loads batched ----
        {
            float f[8];
            int   rows[8];
            bool  ok[8];
            #pragma unroll
            for (int j = 0; j < 8; ++j) {
                rows[j] = gw + j * nwarps;
                ok[j]   = rows[j] < M_TOTAL;           // warp-uniform
                f[j]    = ok[j] ? x[(size_t)rows[j] * IN_F + col] : 0.f;
            }
            #pragma unroll
            for (int j = 0; j < 8; ++j) {
                if (ok[j]) {
                    __nv_bfloat16 hb = __float2bfloat16(f[j]);
                    float res = f[j] - __bfloat162float(hb);
                    __nv_bfloat16 lb = __float2bfloat16(res);
                    size_t base = (size_t)rows[j] * PK + (size_t)k * 64 + lane;
                    g_Xp[base]      = hb;
                    g_Xp[base + 32] = lb;
                }
            }
        }

        // ---- V block: lane holds V[k*32+lane][0..15] ----
        float v[16];
        {
            const float4* vp = reinterpret_cast<const float4*>(
                V + (size_t)(k * 32 + lane) * RANK);
            float4 a0 = vp[0], a1 = vp[1], a2 = vp[2], a3 = vp[3];
            v[0]=a0.x; v[1]=a0.y; v[2]=a0.z; v[3]=a0.w;
            v[4]=a1.x; v[5]=a1.y; v[6]=a1.z; v[7]=a1.w;
            v[8]=a2.x; v[9]=a2.y; v[10]=a2.z; v[11]=a2.w;
            v[12]=a3.x; v[13]=a3.y; v[14]=a3.z; v[15]=a3.w;
        }

        // ---- W': up to 4 rows, W+U loads batched ----
        {
            float w[4], u[4];
            int   rows[4];
            bool  ok[4];
            #pragma unroll
            for (int j = 0; j < 4; ++j) {
                rows[j] = gw + j * nwarps;
                ok[j]   = rows[j] < OUT_F;             // warp-uniform
                w[j]    = ok[j] ? W[(size_t)rows[j] * IN_F + col] : 0.f;
                u[j]    = (ok[j] && lane < 16)
                          ? U[(size_t)rows[j] * RANK + lane] * s_l : 0.f;
            }
            #pragma unroll
            for (int j = 0; j < 4; ++j) {
                if (ok[j]) {                            // warp-uniform
                    float acc = w[j];
                    #pragma unroll
                    for (int r = 0; r < 16; ++r)
                        acc += __shfl_sync(0xFFFFFFFFu, u[j], r) * v[r];
                    __nv_bfloat16 hb = __float2bfloat16(acc);
                    float res = acc - __bfloat162float(hb);
                    __nv_bfloat16 lb = __float2bfloat16(res);
                    size_t base = (size_t)rows[j] * PK + (size_t)k * 64 + lane;
                    g_Wp[base]      = hb;
                    g_Wp[base + 32] = lb;
                }
            }
        }

        // hierarchical arrival: CTA-local named barrier, then one atomic
        asm volatile("bar.sync 2, %0;" :: "r"(bar_cnt) : "memory");
        if (tid == arrive_tid) {
            __threadfence();                     // cumulative: covers CTA's writes
            atomicAdd(&g_cnt[k * 32], 1u);
        }
    }
}

// ===================== tcgen05/TMA machinery (sm_103a cubin only) =============
#if defined(__CUDA_ARCH_FEAT_SM103_ALL)
__device__ __forceinline__ uint32_t elect_one() {
    uint32_t p;
    asm volatile("{\n\t.reg .pred p;\n\telect.sync _|p, 0xFFFFFFFF;\n\tselp.b32 %0, 1, 0, p;\n\t}"
                 : "=r"(p));
    return p;
}
#define MBARRIER_INIT(addr, cnt) \
    asm volatile("mbarrier.init.shared.b64 [%0], %1;" :: "r"(addr), "r"(cnt) : "memory")
#define MBARRIER_ARRIVE(mbar) \
    asm volatile("mbarrier.arrive.shared.b64 _, [%0];" :: "r"((uint32_t)(mbar)) : "memory")
#define MBARRIER_ARRIVE_CLUSTER(mbar, trank) \
    asm volatile("{\n\t.reg .b32 ra;\n\t" \
                 "mapa.shared::cluster.u32 ra, %0, %1;\n\t" \
                 "mbarrier.arrive.shared::cluster.b64 _, [ra];\n\t}" \
                 :: "r"((uint32_t)(mbar)), "r"((uint32_t)(trank)) : "memory")
#define MBARRIER_EXPECT_TX(mbar, bytes) \
    asm volatile("mbarrier.arrive.expect_tx.shared.b64 _, [%0], %1;" \
                 :: "r"((uint32_t)(mbar)), "r"((uint32_t)(bytes)) : "memory")
#define MBARRIER_WAIT_PARITY(mbar, par) do {                                             \
    uint32_t _m = (uint32_t)(mbar); uint32_t _p = (uint32_t)(par); uint32_t _d;          \
    asm volatile("{\n\t.reg .pred p;\n\t"                                                \
        "mbarrier.try_wait.parity.acquire.cta.shared::cta.b64 p, [%1], %2;\n\t"          \
        "selp.b32 %0, 1, 0, p;\n\t}" : "=r"(_d) : "r"(_m), "r"(_p) : "memory");          \
    if (!_d) {                                                                           \
        asm volatile("{\n\t.reg .pred P1;\n\tWL_%=: \n\t"                                \
            "mbarrier.try_wait.parity.acquire.cta.shared::cta.b64 P1, [%0], %1, 0x989680;\n\t" \
            "@P1 bra.uni WD_%=;\n\tbra.uni WL_%=;\n\tWD_%=: \n\t}"                       \
            :: "r"(_m), "r"(_p) : "memory");                                             \
    }                                                                                    \
} while (0)
#define TMA_LOAD_3D_CG2(smem_addr, tmap, c0, c1, c2, mbar) \
    asm volatile( \
        "{\n\t.reg .b32 lb;\n\t" \
        "and.b32 lb, %5, 0xFEFFFFFF;\n\t" \
        "cp.async.bulk.tensor.3d.cta_group::2.shared::cluster.global" \
        ".tile.mbarrier::complete_tx::bytes " \
        "[%0], [%1, {%2, %3, %4}], [lb];\n\t}" \
        :: "r"((uint32_t)(smem_addr)), "l"(tmap), \
           "r"((int)(c0)), "r"((int)(c1)), "r"((int)(c2)), \
           "r"((uint32_t)(mbar)) : "memory")
#define TCGEN05_ALLOC_CG2(sa, n) \
    asm volatile("tcgen05.alloc.cta_group::2.sync.aligned.shared::cta.b32 [%0], %1;" \
                 :: "r"((uint32_t)(sa)), "r"((uint32_t)(n)) : "memory")
#define TCGEN05_RELQ_CG2() \
    asm volatile("tcgen05.relinquish_alloc_permit.cta_group::2.sync.aligned;")
#define TCGEN05_DEALLOC_CG2(t, n) \
    asm volatile("tcgen05.dealloc.cta_group::2.sync.aligned.b32 %0, %1;" \
                 :: "r"(t), "r"((uint32_t)(n)))
#define TCGEN05_COMMIT_MC_CG2(mb) \
    asm volatile("tcgen05.commit.cta_group::2.mbarrier::arrive::one.shared::cluster.multicast::cluster.b64 [%0], %1;" \
                 :: "r"((uint32_t)(mb)), "h"((uint16_t)3) : "memory")
#define TCGEN05_FENCE_AFTER()  asm volatile("tcgen05.fence::after_thread_sync;" ::: "memory")
#define TCGEN05_FENCE_BEFORE() asm volatile("tcgen05.fence::before_thread_sync;" ::: "memory")
#define TCGEN05_WAIT_LD()      asm volatile("tcgen05.wait::ld.sync.aligned;" ::: "memory")
#define CLUSTER_ARRIVE() asm volatile("barrier.cluster.arrive.aligned;" ::: "memory")
#define CLUSTER_WAIT()   asm volatile("barrier.cluster.wait.aligned;" ::: "memory")

// poll a padded prep chunk counter (tile 0 only), then fence to async proxy
#define POLL_CHUNK(kk) do {                                                   \
    unsigned _v; const unsigned* _c = &g_cnt[(kk) * 32];                      \
    while (true) {                                                            \
        asm volatile("ld.acquire.gpu.u32 %0, [%1];" : "=r"(_v) : "l"(_c));    \
        if (_v >= PREP_CTAS) break;                                           \
        asm volatile("nanosleep.u32 128;");                                   \
    }                                                                         \
    asm volatile("fence.proxy.async;" ::: "memory");                          \
} while (0)

#define TCGEN05_LD_X32(r, ta) \
    asm volatile( \
        "tcgen05.ld.sync.aligned.32x32b.x32.b32 " \
        "{%0, %1, %2, %3, %4, %5, %6, %7, " \
        " %8, %9, %10, %11, %12, %13, %14, %15, " \
        " %16, %17, %18, %19, %20, %21, %22, %23, " \
        " %24, %25, %26, %27, %28, %29, %30, %31}, [%32];" \
        : "=r"((r)[0]),  "=r"((r)[1]),  "=r"((r)[2]),  "=r"((r)[3]), \
          "=r"((r)[4]),  "=r"((r)[5]),  "=r"((r)[6]),  "=r"((r)[7]), \
          "=r"((r)[8]),  "=r"((r)[9]),  "=r"((r)[10]), "=r"((r)[11]), \
          "=r"((r)[12]), "=r"((r)[13]), "=r"((r)[14]), "=r"((r)[15]), \
          "=r"((r)[16]), "=r"((r)[17]), "=r"((r)[18]), "=r"((r)[19]), \
          "=r"((r)[20]), "=r"((r)[21]), "=r"((r)[22]), "=r"((r)[23]), \
          "=r"((r)[24]), "=r"((r)[25]), "=r"((r)[26]), "=r"((r)[27]), \
          "=r"((r)[28]), "=r"((r)[29]), "=r"((r)[30]), "=r"((r)[31]) \
        : "r"(ta))

static constexpr uint64_t SMEM_DESC_BASE_SW128 =
    (uint64_t(2) << 61) | (uint64_t(1) << 46) | (uint64_t(64) << 32) | (uint64_t(1) << 16);
#define MAKE_SMEM_DESC(ba) (SMEM_DESC_BASE_SW128 | ((uint64_t)((ba) >> 4) & 0x3FFF))

__device__ __forceinline__ void mma_f16_ss_cg2(uint32_t d, uint64_t a, uint64_t b,
                                               uint32_t idesc, uint32_t acc) {
    asm volatile(
        "{\n\t.reg .pred p;\n\tsetp.ne.u32 p, %4, 0;\n\t"
        "tcgen05.mma.cta_group::2.kind::f16 [%0], %1, %2, %3, "
        "{%5, %5, %5, %5, %5, %5, %5, %5}, p;\n\t}"
        :: "r"(d), "l"(a), "l"(b), "r"(idesc), "r"(acc), "r"(0u) : "memory");
}
#else
__device__ __forceinline__ void ldm4(uint32_t* r, uint32_t addr) {
    asm volatile("ldmatrix.sync.aligned.m8n8.x4.shared.b16 {%0,%1,%2,%3}, [%4];"
                 : "=r"(r[0]), "=r"(r[1]), "=r"(r[2]), "=r"(r[3]) : "r"(addr));
}
__device__ __forceinline__ void mma16816(float* d, const uint32_t* a, const uint32_t* b) {
    asm volatile(
        "mma.sync.aligned.m16n8k16.row.col.f32.bf16.bf16.f32 "
        "{%0,%1,%2,%3}, {%4,%5,%6,%7}, {%8,%9}, {%0,%1,%2,%3};"
        : "+f"(d[0]), "+f"(d[1]), "+f"(d[2]), "+f"(d[3])
        : "r"(a[0]), "r"(a[1]), "r"(a[2]), "r"(a[3]), "r"(b[0]), "r"(b[1]));
}
#endif

// ===================== fused persistent kernel =====================
// grid (2, 74, 1), cluster (2,1,1), 256 threads.
// warp 0: MMA/TMA pipeline (rank0) / TMA producer (rank1)
// warps 1-3: prep only; warps 4-7: prep, then epilogue
__global__ void __launch_bounds__(THREADS, 1) __cluster_dims__(2, 1, 1)
gemm_kernel(float* __restrict__ out,
            const float* __restrict__ x, const float* __restrict__ W,
            const float* __restrict__ U, const float* __restrict__ s,
            const float* __restrict__ V,
            const __grid_constant__ CUtensorMap tmx,
            const __grid_constant__ CUtensorMap tmw)
{
    extern __shared__ char smem[];
    const uint32_t sb = smem_u32(smem);
    const int tid  = threadIdx.x;
    const int lane = tid & 31;
    const int wid  = tid >> 5;
    const int rank = (int)blockIdx.x;
    const int cid  = (int)blockIdx.y;             // cluster id 0..73
    const int lin  = rank + 2 * cid;              // linear CTA id 0..147
    const int NLOC = (NTILES - 1 - cid) / NCLUST + 1;   // 6 or 7 local tiles

#if defined(__CUDA_ARCH_FEAT_SM103_ALL)
    const uint32_t FULL = sb + 64;    // 5 slots
    const uint32_t MBM  = sb + 128;   // 4 slots
    const uint32_t TILE = sb + 192;   // 2 slots (tile-done, multicast)
    const uint32_t EPI  = sb + 256;   // 2 slots (buffer free, count 2, on rank0)

    if (tid == 0) {
        for (int i = 0; i < 5; ++i) MBARRIER_INIT(FULL + i * 8, 1);
        for (int i = 0; i < 4; ++i) MBARRIER_INIT(MBM + i * 8, 1);
        for (int i = 0; i < 2; ++i) MBARRIER_INIT(TILE + i * 8, 1);
        for (int i = 0; i < 2; ++i) MBARRIER_INIT(EPI + i * 8, 2);
    }
    if (wid == 0) TCGEN05_ALLOC_CG2(sb + 0, 512);   // two 256-col accumulators
    __syncthreads();
    uint32_t tmem;
    asm volatile("ld.shared.b32 %0, [%1];" : "=r"(tmem) : "r"(sb + 0));

    CLUSTER_ARRIVE();
    CLUSTER_WAIT();

    const int L = NLOC * NK_TC;                   // local k-iterations

    auto tma_pair = [&](int g, uint32_t stb, uint32_t mbar) {
        const int j = g >> 7, k = g & 127;
        const int t = cid + NCLUST * j;
        const int a_row = (t % M_TILES) * 256 + rank * 128;
        const int w_row = (t / M_TILES) * 256 + rank * 128;
        TMA_LOAD_3D_CG2(stb,          &tmx, 64 * k, a_row, 0, mbar);
        TMA_LOAD_3D_CG2(stb + SW_OFF, &tmw, 64 * k, w_row, 0, mbar);
    };

    if (wid == 0) {
        if (elect_one()) {
            if (rank == 0) {
                #pragma unroll
                for (int p = 0; p < 4; ++p) {
                    POLL_CHUNK(p);
                    MBARRIER_EXPECT_TX(FULL + p * 8, 2 * STG_TC);
                    tma_pair(p, sb + HDR_TC + p * STG_TC, FULL + p * 8);
                }
                for (int g = 0; g < L; ++g) {
                    const int tl = g >> 7, k = g & 127;
                    if (k == 0 && tl >= 2)
                        MBARRIER_WAIT_PARITY(EPI + (tl & 1) * 8, ((tl >> 1) - 1) & 1);
                    MBARRIER_WAIT_PARITY(FULL + (g % 5) * 8, (g / 5) & 1);
                    const uint32_t stb = sb + HDR_TC + (g % NSTAGE) * STG_TC;
                    const uint64_t dA  = MAKE_SMEM_DESC(stb);
                    const uint64_t dW  = MAKE_SMEM_DESC(stb + SW_OFF);
                    const uint32_t D   = tmem + (tl & 1) * 256;
                    const uint32_t first = (k == 0) ? 0u : 1u;
                    mma_f16_ss_cg2(D, dA + 0, dW + 0, IDESC_CG2, first);
                    mma_f16_ss_cg2(D, dA + 2, dW + 2, IDESC_CG2, 1u);
                    mma_f16_ss_cg2(D, dA + 0, dW + 4, IDESC_CG2, 1u);
                    mma_f16_ss_cg2(D, dA + 2, dW + 6, IDESC_CG2, 1u);
                    mma_f16_ss_cg2(D, dA + 4, dW + 0, IDESC_CG2, 1u);
                    mma_f16_ss_cg2(D, dA + 6, dW + 2, IDESC_CG2, 1u);
                    TCGEN05_COMMIT_MC_CG2(MBM + (g % 4) * 8);
                    if (k == 127) TCGEN05_COMMIT_MC_CG2(TILE + (tl & 1) * 8);
                    const int nxt = g + 4;
                    if (nxt < L) {
                        if (g >= 1) MBARRIER_WAIT_PARITY(MBM + ((g - 1) % 4) * 8, ((g - 1) / 4) & 1);
                        if (nxt < 128) POLL_CHUNK(nxt);
                        MBARRIER_EXPECT_TX(FULL + (nxt % 5) * 8, 2 * STG_TC);
                        tma_pair(nxt, sb + HDR_TC + (nxt % NSTAGE) * STG_TC, FULL + (nxt % 5) * 8);
                    }
                }
            } else {
                #pragma unroll
                for (int p = 0; p < 4; ++p) {
                    POLL_CHUNK(p);
                    tma_pair(p, sb + HDR_TC + p * STG_TC, FULL + p * 8);
                }
                for (int g = 0; g + 4 < L; ++g) {
                    if (g >= 1) MBARRIER_WAIT_PARITY(MBM + ((g - 1) % 4) * 8, ((g - 1) / 4) & 1);
                    const int nxt = g + 4;
                    if (nxt < 128) POLL_CHUNK(nxt);
                    tma_pair(nxt, sb + HDR_TC + (nxt % NSTAGE) * STG_TC, FULL + (nxt % 5) * 8);
                }
            }
        }
    } else {
        // ---- prep (warps 1-7 of all CTAs), overlapped with the pipeline ----
        // barrier id 2, 224 threads; arriving thread tid==32 (warp 1 lane 0)
        prep_warp(lin * 7 + (wid - 1), 148 * 7, lane, tid, 32, 224u,
                  x, W, U, s, V);
    }

    // consumers: warps 4-7 of both CTAs drain finished accumulators (after prep)
    if (wid >= 4) {
        const int sub = wid - 4;
        for (int tl = 0; tl < NLOC; ++tl) {
            MBARRIER_WAIT_PARITY(TILE + (tl & 1) * 8, (tl >> 1) & 1);
            TCGEN05_FENCE_AFTER();
            const int t = cid + NCLUST * tl;
            const int row = (t % M_TILES) * 256 + rank * 128 + sub * 32 + lane;
            const int n_b = (t / M_TILES) * 256;
            const uint32_t D = tmem + (tl & 1) * 256;
            #pragma unroll
            for (int cc = 0; cc < 8; ++cc) {
                uint32_t regs[32];
                TCGEN05_LD_X32(regs, D + cc * 32);
                TCGEN05_WAIT_LD();
                float* dst = out + (size_t)row * OUT_F + n_b + cc * 32;
                #pragma unroll
                for (int q = 0; q < 32; q += 4)
                    *reinterpret_cast<float4*>(dst + q) =
                        make_float4(__uint_as_float(regs[q]), __uint_as_float(regs[q + 1]),
                                    __uint_as_float(regs[q + 2]), __uint_as_float(regs[q + 3]));
            }
            TCGEN05_FENCE_BEFORE();
            asm volatile("bar.sync 1, 128;" ::: "memory");
            if (tid == 128) {
                if (rank == 0) MBARRIER_ARRIVE(EPI + (tl & 1) * 8);
                else           MBARRIER_ARRIVE_CLUSTER(EPI + (tl & 1) * 8, 0);
            }
        }
    }

    __syncthreads();
    CLUSTER_ARRIVE();
    CLUSTER_WAIT();
    if (wid == 0) {
        TCGEN05_RELQ_CG2();
        TCGEN05_DEALLOC_CG2(tmem, 512);
    }
    CLUSTER_ARRIVE();
    CLUSTER_WAIT();

#else
    // ============ fallback (mma.sync): self-prep + device barrier + tile loop ==
    prep_warp(lin * 8 + wid, 148 * 8, lane, tid, 0, 256u, x, W, U, s, V);
    __syncthreads();
    if (tid == 0) {
        __threadfence();
        atomicAdd(&g_cnt[128 * 32], 1u);
        unsigned v; const unsigned* c = &g_cnt[128 * 32];
        do { asm volatile("ld.acquire.gpu.u32 %0, [%1];" : "=r"(v) : "l"(c)); } while (v < 148u);
    }
    __syncthreads();

    const int wm = wid & 3;
    const int wn = wid >> 2;

    for (int tl = 0; tl < NLOC; ++tl) {
        const int t = cid + NCLUST * tl;
        const int mb  = (t % M_TILES) * 256 + rank * 128;
        const int n_b = (t / M_TILES) * 256;

        for (int nhalf = 0; nhalf < 2; ++nhalf) {
            const int n_base_fb = n_b + nhalf * 128;
            __syncthreads();

            auto issue = [&](int st, int kidx) {
                const uint32_t stb = sb + st * STG_FB;
                const int g = kidx;
                const int r0 = tid >> 2, c = tid & 3;
                #pragma unroll
                for (int j = 0; j < 2; ++j) {
                    int r = r0 + j * 64;
                    uint32_t rowoff = (uint32_t)(r * (ROWH * 2) + c * 16);
                    size_t bx = (size_t)(mb + r) * PK + (size_t)g * 64 + c * 8;
                    size_t bw = (size_t)(n_base_fb + r) * PK + (size_t)g * 64 + c * 8;
                    cp16(stb + AH_B + rowoff, &g_Xp[bx]);
                    cp16(stb + AL_B + rowoff, &g_Xp[bx + 32]);
                    cp16(stb + BH_B + rowoff, &g_Wp[bw]);
                    cp16(stb + BL_B + rowoff, &g_Wp[bw + 32]);
                }
            };

            issue(0, 0); CP_COMMIT();
            issue(1, 1); CP_COMMIT();

            float acc[2][8][4];
            #pragma unroll
            for (int a = 0; a < 2; ++a)
                #pragma unroll
                for (int b = 0; b < 8; ++b)
                    #pragma unroll
                    for (int cidx = 0; cidx < 4; ++cidx) acc[a][b][cidx] = 0.f;

            const int aRow  = wm * 32 + (lane & 15);
            const int aColH = (lane >> 4) * 8;
            const int bIdx  = lane & 7;
            const int bGrp  = lane >> 3;
            const int bRow  = wn * 64 + ((bGrp & 2) << 2) + bIdx;
            const int bColH = (bGrp & 1) * 8;

            for (int i = 0; i < NK_FB; ++i) {
                CP_WAIT(1);
                __syncthreads();
                if (i + 2 < NK_FB) issue((i + 2) % NSTAGE_FB, i + 2);
                CP_COMMIT();

                const uint32_t stb = sb + (i % NSTAGE_FB) * STG_FB;
                #pragma unroll
                for (int k16 = 0; k16 < 2; ++k16) {
                    uint32_t ah[2][4], al[2][4];
                    #pragma unroll
                    for (int mt = 0; mt < 2; ++mt) {
                        uint32_t off = (uint32_t)((aRow + mt * 16) * (ROWH * 2) +
                                                  (k16 * 16 + aColH) * 2);
                        ldm4(ah[mt], stb + AH_B + off);
                        ldm4(al[mt], stb + AL_B + off);
                    }
                    #pragma unroll
                    for (int j = 0; j < 4; ++j) {
                        uint32_t off = (uint32_t)((bRow + j * 16) * (ROWH * 2) +
                                                  (k16 * 16 + bColH) * 2);
                        uint32_t bh[4];
                        ldm4(bh, stb + BH_B + off);
                        #pragma unroll
                        for (int mt = 0; mt < 2; ++mt) {
                            mma16816(acc[mt][2 * j + 0], ah[mt], bh + 0);
                            mma16816(acc[mt][2 * j + 1], ah[mt], bh + 2);
                            mma16816(acc[mt][2 * j + 0], al[mt], bh + 0);
                            mma16816(acc[mt][2 * j + 1], al[mt], bh + 2);
                        }
                    }
                    #pragma unroll
                    for (int j = 0; j < 4; ++j) {
                        uint32_t off = (uint32_t)((bRow + j * 16) * (ROWH * 2) +
                                                  (k16 * 16 + bColH) * 2);
                        uint32_t bl[4];
                        ldm4(bl, stb + BL_B + off);
                        #pragma unroll
                        for (int mt = 0; mt < 2; ++mt) {
                            mma16816(acc[mt][2 * j + 0], ah[mt], bl + 0);
                            mma16816(acc[mt][2 * j + 1], ah[mt], bl + 2);
                        }
                    }
                }
            }

            #pragma unroll
            for (int mt = 0; mt < 2; ++mt) {
                const int row0 = mb + wm * 32 + mt * 16 + (lane >> 2);
                #pragma unroll
                for (int nb = 0; nb < 8; ++nb) {
                    const int col = n_base_fb + wn * 64 + nb * 8 + (lane & 3) * 2;
                    *reinterpret_cast<float2*>(out + (size_t)row0 * OUT_F + col) =
                        make_float2(acc[mt][nb][0], acc[mt][nb][1]);
                    *reinterpret_cast<float2*>(out + (size_t)(row0 + 8) * OUT_F + col) =
                        make_float2(acc[mt][nb][2], acc[mt][nb][3]);
                }
            }
        }
    }
#endif
}

// ===================== harness entry =====================
typedef CUresult (*PFN_encodeTiled_t)(
    CUtensorMap*, CUtensorMapDataType, cuuint32_t, void*,
    const cuuint64_t*, const cuuint64_t*, const cuuint32_t*, const cuuint32_t*,
    CUtensorMapInterleave, CUtensorMapSwizzle, CUtensorMapL2promotion,
    CUtensorMapFloatOOBfill);

extern "C" void kernel_launch(void* const* d_in, const int* in_sizes, int n_in,
                              void* d_out, int out_size)
{
    const float* x = (const float*)d_in[0];
    const float* W = (const float*)d_in[1];
    const float* U = (const float*)d_in[2];
    const float* s = (const float*)d_in[3];
    const float* V = (const float*)d_in[4];
    float* out = (float*)d_out;
    (void)in_sizes; (void)n_in; (void)out_size;

    // reset chunk-ready counters (graph-capturable, no allocation)
    void* pc = nullptr;
    cudaGetSymbolAddress(&pc, g_cnt);
    cudaMemsetAsync(pc, 0, sizeof(g_cnt));

    alignas(64) CUtensorMap tmx{}, tmw{};
    {
        void* px = nullptr; cudaGetSymbolAddress(&px, g_Xp);
        void* pw = nullptr; cudaGetSymbolAddress(&pw, g_Wp);
        PFN_encodeTiled_t enc = nullptr;
        cudaDriverEntryPointQueryResult st{};
        cudaGetDriverEntryPoint("cuTensorMapEncodeTiled", (void**)&enc,
                                cudaEnableDefault, &st);
        if (enc) {
            cuuint32_t box[3] = {64, 128, 1};
            cuuint32_t es[3]  = {1, 1, 1};
            cuuint64_t dimsX[3] = {(cuuint64_t)PK, (cuuint64_t)M_TOTAL, 1};
            cuuint64_t strX[2]  = {(cuuint64_t)PK * 2, (cuuint64_t)PK * 2 * M_TOTAL};
            enc(&tmx, CU_TENSOR_MAP_DATA_TYPE_BFLOAT16, 3, px, dimsX, strX, box, es,
                CU_TENSOR_MAP_INTERLEAVE_NONE, CU_TENSOR_MAP_SWIZZLE_128B,
                CU_TENSOR_MAP_L2_PROMOTION_L2_128B, CU_TENSOR_MAP_FLOAT_OOB_FILL_NONE);
            cuuint64_t dimsW[3] = {(cuuint64_t)PK, (cuuint64_t)OUT_F, 1};
            cuuint64_t strW[2]  = {(cuuint64_t)PK * 2, (cuuint64_t)PK * 2 * OUT_F};
            enc(&tmw, CU_TENSOR_MAP_DATA_TYPE_BFLOAT16, 3, pw, dimsW, strW, box, es,
                CU_TENSOR_MAP_INTERLEAVE_NONE, CU_TENSOR_MAP_SWIZZLE_128B,
                CU_TENSOR_MAP_L2_PROMOTION_L2_128B, CU_TENSOR_MAP_FLOAT_OOB_FILL_NONE);
        }
    }

    cudaFuncSetAttribute(gemm_kernel, cudaFuncAttributeMaxDynamicSharedMemorySize, SMEM_DYN);
    gemm_kernel<<<dim3(2, NCLUST, 1), THREADS, SMEM_DYN>>>(out, x, W, U, s, V, tmx, tmw);
}